// round 3
// baseline (speedup 1.0000x reference)
#include <cuda_runtime.h>

// Comparator4Bit: A,B are [N,4] float32 with exact {0,1} entries (MSB first).
// Outputs: a_gt_b [N], a_eq_b [N], concatenated into d_out (2N floats).
// Entries are exactly 0/1 -> pack to 4-bit int and compare; bit-identical to
// the reference boolean-arithmetic formulas.
//
// R2: 8 rows per thread (2 float4 stores per output stream). 16 independent
// 128-bit loads per thread to deepen MLP and push DRAM saturation.

__global__ __launch_bounds__(256) void cmp4_kernel(
    const float4* __restrict__ A,   // N rows, one float4 per row
    const float4* __restrict__ B,
    float4* __restrict__ gt_out,    // N/4 float4
    float4* __restrict__ eq_out,    // N/4 float4
    int n_oct)                      // N/8
{
    int t = blockIdx.x * blockDim.x + threadIdx.x;
    if (t >= n_oct) return;

    // Front-batch all 16 loads (8 rows x A,B) for max memory-level parallelism.
    float4 a[8], b[8];
    #pragma unroll
    for (int r = 0; r < 8; r++) {
        a[r] = __ldg(&A[t * 8 + r]);
        b[r] = __ldg(&B[t * 8 + r]);
    }

    float gt[8], eq[8];
    #pragma unroll
    for (int r = 0; r < 8; r++) {
        int av = ((int)a[r].x << 3) | ((int)a[r].y << 2) | ((int)a[r].z << 1) | (int)a[r].w;
        int bv = ((int)b[r].x << 3) | ((int)b[r].y << 2) | ((int)b[r].z << 1) | (int)b[r].w;
        gt[r] = (av > bv)  ? 1.0f : 0.0f;
        eq[r] = (av == bv) ? 1.0f : 0.0f;
    }

    gt_out[t * 2 + 0] = make_float4(gt[0], gt[1], gt[2], gt[3]);
    gt_out[t * 2 + 1] = make_float4(gt[4], gt[5], gt[6], gt[7]);
    eq_out[t * 2 + 0] = make_float4(eq[0], eq[1], eq[2], eq[3]);
    eq_out[t * 2 + 1] = make_float4(eq[4], eq[5], eq[6], eq[7]);
}

extern "C" void kernel_launch(void* const* d_in, const int* in_sizes, int n_in,
                              void* d_out, int out_size)
{
    const float4* A = (const float4*)d_in[0];
    const float4* B = (const float4*)d_in[1];
    int n_rows = in_sizes[0] / 4;          // N = 2^23
    int n_oct  = n_rows / 8;               // rows per thread = 8

    float* out = (float*)d_out;
    float4* gt_out = (float4*)out;                 // first N floats
    float4* eq_out = (float4*)(out + n_rows);      // next N floats

    int threads = 256;
    int blocks = (n_oct + threads - 1) / threads;
    cmp4_kernel<<<blocks, threads>>>(A, B, gt_out, eq_out, n_oct);
}

// round 5
// speedup vs baseline: 1.4197x; 1.4197x over previous
#include <cuda_runtime.h>

// Comparator4Bit: A,B are [N,4] float32 with exact {0,1} entries (MSB first).
// Outputs: a_gt_b [N], a_eq_b [N], concatenated into d_out (2N floats).
//
// R4: R3 layout (block-contiguous tiles, warp-stride => perfectly coalesced
// 128-bit loads, 4 lines/warp-LDG) with the bit-extraction bug fixed: test
// each lane against zero (values are exactly 0.0f or 1.0f).

#define ROWS_PER_THREAD 8
#define BLOCK_THREADS   256

__global__ __launch_bounds__(BLOCK_THREADS) void cmp4_kernel(
    const uint4* __restrict__ A,    // one uint4 per row
    const uint4* __restrict__ B,
    float* __restrict__ gt_out,     // N floats
    float* __restrict__ eq_out)     // N floats
{
    const int tile = blockIdx.x * (BLOCK_THREADS * ROWS_PER_THREAD);

    // Front-batch all 16 loads; each is warp-coalesced (consecutive lanes ->
    // consecutive 16B -> 4 cache lines per warp LDG).
    uint4 a[ROWS_PER_THREAD], b[ROWS_PER_THREAD];
    #pragma unroll
    for (int k = 0; k < ROWS_PER_THREAD; k++) {
        int row = tile + k * BLOCK_THREADS + threadIdx.x;
        a[k] = __ldg(&A[row]);
        b[k] = __ldg(&B[row]);
    }

    #pragma unroll
    for (int k = 0; k < ROWS_PER_THREAD; k++) {
        int row = tile + k * BLOCK_THREADS + threadIdx.x;
        // Values are exactly 0.0f (0x00000000) or 1.0f (0x3F800000):
        // nonzero bit pattern == logical 1.
        int av = ((a[k].x != 0u) << 3) | ((a[k].y != 0u) << 2) |
                 ((a[k].z != 0u) << 1) |  (a[k].w != 0u);
        int bv = ((b[k].x != 0u) << 3) | ((b[k].y != 0u) << 2) |
                 ((b[k].z != 0u) << 1) |  (b[k].w != 0u);
        gt_out[row] = (av > bv)  ? 1.0f : 0.0f;
        eq_out[row] = (av == bv) ? 1.0f : 0.0f;
    }
}

extern "C" void kernel_launch(void* const* d_in, const int* in_sizes, int n_in,
                              void* d_out, int out_size)
{
    const uint4* A = (const uint4*)d_in[0];
    const uint4* B = (const uint4*)d_in[1];
    int n_rows = in_sizes[0] / 4;          // N = 2^23

    float* out = (float*)d_out;
    float* gt_out = out;                   // first N floats
    float* eq_out = out + n_rows;          // next N floats

    int rows_per_block = BLOCK_THREADS * ROWS_PER_THREAD;   // 2048
    int blocks = n_rows / rows_per_block;                   // N is a power of two
    cmp4_kernel<<<blocks, BLOCK_THREADS>>>(A, B, gt_out, eq_out);
}